// round 2
// baseline (speedup 1.0000x reference)
#include <cuda_runtime.h>
#include <math_constants.h>

// Problem constants
#define Bn   64
#define Hn   28
#define Wn   28
#define HW   784            // Hn*Wn
#define Cn   512
#define CT   32             // channels per block
#define NTB  512            // threads per block
#define NGRP (NTB / 8)      // 64 threads share each channel-quad group
#define TS   788            // padded template row stride (floats): %4==0 for f4 align,
                            // 197 % 32 = 5 (odd) -> conflict-free scalar LDS in step C
#define XS   32             // x tile row stride (floats)

// SMEM layout (floats):
//   xs   : HW*XS          = 25088 f = 100352 B   x tile, [s][cc]
//   ts   : CT*TS          = 25216 f = 100864 B   templates, [cc][s] (padded)
//   rval : CT*NGRP        =  2048 f =   8192 B   partial argmax values
//   ridx : CT*NGRP (int)  =  2048 i =   8192 B   partial argmax indices
//   tbase: CT (int)       =    32 i =    128 B   gathered row index per channel
#define SMEM_FLOATS (HW*XS + CT*TS + CT*NGRP)
#define SMEM_BYTES  (SMEM_FLOATS*4 + CT*NGRP*4 + CT*4)   // 217,728 B

__global__ __launch_bounds__(NTB, 1)
void fused_peak_template_relu(const float* __restrict__ x,
                              const float* __restrict__ tp,
                              float* __restrict__ out)
{
    extern __shared__ float smem[];
    float* xs    = smem;                         // [s*XS + cc]
    float* ts    = xs + HW * XS;                 // [cc*TS + s]
    float* rval  = ts + CT * TS;                 // [cc*NGRP + g]
    int*   ridx  = (int*)(rval + CT * NGRP);     // [cc*NGRP + g]
    int*   tbase = ridx + CT * NGRP;             // [cc]

    const int b    = blockIdx.y;
    const int c0   = blockIdx.x * CT;
    const int tid  = threadIdx.x;
    const int grp  = tid & 7;        // which channel quad (0..7)
    const int cq   = grp * 4;        // channel offset within tile
    const int srow = tid >> 3;       // 0..63, spatial phase

    const float* xb = x   + (size_t)b * HW * Cn + c0;
    float*       ob = out + (size_t)b * HW * Cn + c0;

    // ---- Step A: stream x tile into SMEM, running argmax per channel ----
    float bv0 = -CUDART_INF_F, bv1 = -CUDART_INF_F;
    float bv2 = -CUDART_INF_F, bv3 = -CUDART_INF_F;
    int bi0 = 0, bi1 = 0, bi2 = 0, bi3 = 0;

    #pragma unroll 4
    for (int s = srow; s < HW; s += NGRP) {
        float4 v = *(const float4*)(xb + (size_t)s * Cn + cq);
        *(float4*)(xs + s * XS + cq) = v;
        // strictly-greater keeps the EARLIEST index within this thread's
        // increasing-s sequence (matches jnp.argmax first-occurrence).
        if (v.x > bv0) { bv0 = v.x; bi0 = s; }
        if (v.y > bv1) { bv1 = v.y; bi1 = s; }
        if (v.z > bv2) { bv2 = v.z; bi2 = s; }
        if (v.w > bv3) { bv3 = v.w; bi3 = s; }
    }
    rval[(cq + 0) * NGRP + srow] = bv0; ridx[(cq + 0) * NGRP + srow] = bi0;
    rval[(cq + 1) * NGRP + srow] = bv1; ridx[(cq + 1) * NGRP + srow] = bi1;
    rval[(cq + 2) * NGRP + srow] = bv2; ridx[(cq + 2) * NGRP + srow] = bi2;
    rval[(cq + 3) * NGRP + srow] = bv3; ridx[(cq + 3) * NGRP + srow] = bi3;
    __syncthreads();

    // ---- Final argmax reduction: one thread per channel ----
    // Cross-thread tie-break: lowest spatial index wins.
    if (tid < CT) {
        const float* rv = rval + tid * NGRP;
        const int*   ri = ridx + tid * NGRP;
        float bv = -CUDART_INF_F; int bi = HW;
        #pragma unroll 8
        for (int k = 0; k < NGRP; ++k) {
            float v = rv[k]; int i = ri[k];
            if (v > bv || (v == bv && i < bi)) { bv = v; bi = i; }
        }
        tbase[tid] = b * HW + bi;    // row index into t_p (row = 784 floats)
    }
    __syncthreads();

    // ---- Step B: gather template rows (contiguous 3136 B each) into SMEM ----
    {
        const int wid  = tid >> 5;
        const int lane = tid & 31;
        #pragma unroll
        for (int cc = wid; cc < CT; cc += NTB / 32) {
            const float4* row = (const float4*)(tp + (size_t)tbase[cc] * HW);
            float* dst = ts + cc * TS;
            #pragma unroll
            for (int s4 = lane; s4 < HW / 4; s4 += 32) {
                float4 v = row[s4];
                *(float4*)(dst + s4 * 4) = v;
            }
        }
    }
    __syncthreads();

    // ---- Step C: out = relu(x * template), float4 stores ----
    #pragma unroll 4
    for (int s = srow; s < HW; s += NGRP) {
        float4 v = *(const float4*)(xs + s * XS + cq);
        float t0 = ts[(cq + 0) * TS + s];
        float t1 = ts[(cq + 1) * TS + s];
        float t2 = ts[(cq + 2) * TS + s];
        float t3 = ts[(cq + 3) * TS + s];
        float4 o;
        o.x = fmaxf(v.x * t0, 0.0f);
        o.y = fmaxf(v.y * t1, 0.0f);
        o.z = fmaxf(v.z * t2, 0.0f);
        o.w = fmaxf(v.w * t3, 0.0f);
        *(float4*)(ob + (size_t)s * Cn + cq) = o;
    }
}

extern "C" void kernel_launch(void* const* d_in, const int* in_sizes, int n_in,
                              void* d_out, int out_size)
{
    const float* x  = (const float*)d_in[0];
    const float* tp = (const float*)d_in[1];
    // Defensive: identify tensors by element count (x: 25,690,112; t_p: 39,337,984)
    if (n_in >= 2 && in_sizes[0] == Bn * HW * HW) {
        const float* t = x; x = tp; tp = t;
    }
    float* out = (float*)d_out;

    // Opt into >48KB dynamic SMEM. Host-side attribute set, not a stream op,
    // so legal under graph capture. If it ever fails, fall through — the
    // subsequent launch will then fail visibly rather than silently.
    static int attr_ok = -1;
    if (attr_ok < 0) {
        cudaError_t e = cudaFuncSetAttribute(
            fused_peak_template_relu,
            cudaFuncAttributeMaxDynamicSharedMemorySize, SMEM_BYTES);
        attr_ok = (e == cudaSuccess) ? 1 : 0;
    }

    dim3 grid(Cn / CT, Bn);   // (16, 64) = 1024 blocks
    fused_peak_template_relu<<<grid, NTB, SMEM_BYTES>>>(x, tp, out);
}

// round 4
// speedup vs baseline: 1.2080x; 1.2080x over previous
#include <cuda_runtime.h>
#include <math_constants.h>

// Problem constants
#define Bn   64
#define HW   784            // 28*28 spatial
#define Cn   512
#define CT   16             // channels per block
#define NTB  256            // threads per block
#define NW   (NTB / 32)     // 8 warps
#define TS   788            // padded template row stride (floats); 197%32=5 (odd)
                            // -> conflict-free scalar LDS in apply phase

// SMEM (floats/ints):
//   ts    : CT*TS  = 12608 f = 50432 B   templates, [cc][s]
//   pval  : CT*NW  =   128 f =   512 B   per-warp argmax partial values
//   pidx  : CT*NW  =   128 i =   512 B   per-warp argmax partial indices
//   tbase : CT     =    16 i =    64 B   gathered t_p row index per channel
#define SMEM_BYTES (CT*TS*4 + CT*NW*4 + CT*NW*4 + CT*4)   // 51,520 B

__global__ __launch_bounds__(NTB, 4)
void fused_peak_template_relu(const float* __restrict__ x,
                              const float* __restrict__ tp,
                              float* __restrict__ out)
{
    extern __shared__ float smem[];
    float* ts    = smem;                      // [cc*TS + s]
    float* pval  = ts + CT * TS;              // [cc*NW + w]
    int*   pidx  = (int*)(pval + CT * NW);    // [cc*NW + w]
    int*   tbase = pidx + CT * NW;            // [cc]

    const int b    = blockIdx.y;
    const int c0   = blockIdx.x * CT;
    const int tid  = threadIdx.x;
    const int lane = tid & 31;
    const int wid  = tid >> 5;
    const int grp  = tid & 3;        // channel quad (0..3)
    const int cq   = grp * 4;        // channel offset within tile
    const int srow = tid >> 2;       // 0..63 spatial phase

    const float* xb = x   + (size_t)b * HW * Cn + c0;
    float*       ob = out + (size_t)b * HW * Cn + c0;

    // ---- Step A: stream x, per-thread running argmax for 4 channels ----
    float bv0 = -CUDART_INF_F, bv1 = -CUDART_INF_F;
    float bv2 = -CUDART_INF_F, bv3 = -CUDART_INF_F;
    int bi0 = 0, bi1 = 0, bi2 = 0, bi3 = 0;

    #pragma unroll 4
    for (int s = srow; s < HW; s += 64) {
        float4 v = *(const float4*)(xb + (size_t)s * Cn + cq);
        // strict > keeps the earliest index within this thread's ascending s
        if (v.x > bv0) { bv0 = v.x; bi0 = s; }
        if (v.y > bv1) { bv1 = v.y; bi1 = s; }
        if (v.z > bv2) { bv2 = v.z; bi2 = s; }
        if (v.w > bv3) { bv3 = v.w; bi3 = s; }
    }

    // ---- Warp shuffle reduce: lanes {grp, grp+4, ..., grp+28} share channels ----
    const unsigned m = 0xFFFFFFFFu;
    #pragma unroll
    for (int off = 16; off >= 4; off >>= 1) {
        float ov; int oi;
        ov = __shfl_down_sync(m, bv0, off); oi = __shfl_down_sync(m, bi0, off);
        if (ov > bv0 || (ov == bv0 && oi < bi0)) { bv0 = ov; bi0 = oi; }
        ov = __shfl_down_sync(m, bv1, off); oi = __shfl_down_sync(m, bi1, off);
        if (ov > bv1 || (ov == bv1 && oi < bi1)) { bv1 = ov; bi1 = oi; }
        ov = __shfl_down_sync(m, bv2, off); oi = __shfl_down_sync(m, bi2, off);
        if (ov > bv2 || (ov == bv2 && oi < bi2)) { bv2 = ov; bi2 = oi; }
        ov = __shfl_down_sync(m, bv3, off); oi = __shfl_down_sync(m, bi3, off);
        if (ov > bv3 || (ov == bv3 && oi < bi3)) { bv3 = ov; bi3 = oi; }
    }
    if (lane < 4) {   // lane == grp holds the warp result for channels cq..cq+3
        pval[(cq + 0) * NW + wid] = bv0; pidx[(cq + 0) * NW + wid] = bi0;
        pval[(cq + 1) * NW + wid] = bv1; pidx[(cq + 1) * NW + wid] = bi1;
        pval[(cq + 2) * NW + wid] = bv2; pidx[(cq + 2) * NW + wid] = bi2;
        pval[(cq + 3) * NW + wid] = bv3; pidx[(cq + 3) * NW + wid] = bi3;
    }
    __syncthreads();

    // ---- Final reduce: 16 threads, 8 partials each (idx tie-break = lowest) ----
    if (tid < CT) {
        const float* pv = pval + tid * NW;
        const int*   pi = pidx + tid * NW;
        float bv = -CUDART_INF_F; int bi = HW;
        #pragma unroll
        for (int k = 0; k < NW; ++k) {
            float v = pv[k]; int i = pi[k];
            if (v > bv || (v == bv && i < bi)) { bv = v; bi = i; }
        }
        tbase[tid] = b * HW + bi;
    }
    __syncthreads();

    // ---- Step B: gather template rows (3136 B contiguous each) into SMEM ----
    #pragma unroll
    for (int cc = wid; cc < CT; cc += NW) {
        const float4* row = (const float4*)(tp + (size_t)tbase[cc] * HW);
        float* dst = ts + cc * TS;
        #pragma unroll
        for (int s4 = lane; s4 < HW / 4; s4 += 32) {
            float4 v = row[s4];
            *(float4*)(dst + s4 * 4) = v;
        }
    }
    __syncthreads();

    // ---- Step C: out = relu(x * template); x re-read hits L2 (tile just read) ----
    #pragma unroll 4
    for (int s = srow; s < HW; s += 64) {
        float4 v = *(const float4*)(xb + (size_t)s * Cn + cq);
        float t0 = ts[(cq + 0) * TS + s];
        float t1 = ts[(cq + 1) * TS + s];
        float t2 = ts[(cq + 2) * TS + s];
        float t3 = ts[(cq + 3) * TS + s];
        float4 o;
        o.x = fmaxf(v.x * t0, 0.0f);
        o.y = fmaxf(v.y * t1, 0.0f);
        o.z = fmaxf(v.z * t2, 0.0f);
        o.w = fmaxf(v.w * t3, 0.0f);
        *(float4*)(ob + (size_t)s * Cn + cq) = o;
    }
}

extern "C" void kernel_launch(void* const* d_in, const int* in_sizes, int n_in,
                              void* d_out, int out_size)
{
    const float* x  = (const float*)d_in[0];
    const float* tp = (const float*)d_in[1];
    // Defensive: identify tensors by element count (x: 25,690,112; t_p: 39,337,984)
    if (n_in >= 2 && in_sizes[0] == Bn * HW * HW) {
        const float* t = x; x = tp; tp = t;
    }
    float* out = (float*)d_out;

    // Host-side attribute set (idempotent, not a stream op — capture-legal).
    cudaFuncSetAttribute(fused_peak_template_relu,
                         cudaFuncAttributeMaxDynamicSharedMemorySize, SMEM_BYTES);

    dim3 grid(Cn / CT, Bn);   // (32, 64) = 2048 blocks
    fused_peak_template_relu<<<grid, NTB, SMEM_BYTES>>>(x, tp, out);
}

// round 5
// speedup vs baseline: 1.2239x; 1.0131x over previous
#include <cuda_runtime.h>
#include <math_constants.h>

// Problem constants
#define Bn   64
#define HW   784            // 28*28 spatial
#define Cn   512
#define CT   16             // channels per block
#define NTB  384            // threads per block (12 warps)
#define NW   (NTB / 32)     // 12 warps
#define NSP  (NTB / 4)      // 96 spatial phases
#define TS   788            // padded template row stride (floats), mult of 4

// SMEM:
//   ts    : CT*TS  floats = 50432 B   templates, [cc][s^swz]
//   pval  : CT*NW  floats =   768 B
//   pidx  : CT*NW  ints   =   768 B
//   tbase : CT     ints   =    64 B
#define SMEM_BYTES (CT*TS*4 + CT*NW*4 + CT*NW*4 + CT*4)   // 52,032 B -> 4 CTAs/SM

__global__ __launch_bounds__(NTB, 4)
void fused_peak_template_relu(const float* __restrict__ x,
                              const float* __restrict__ tp,
                              float* __restrict__ out)
{
    extern __shared__ float smem[];
    float* ts    = smem;                      // [cc*TS + (s ^ 8*((cc>>3)&1))]
    float* pval  = ts + CT * TS;              // [cc*NW + w]
    int*   pidx  = (int*)(pval + CT * NW);    // [cc*NW + w]
    int*   tbase = pidx + CT * NW;            // [cc]

    const int b    = blockIdx.y;
    const int c0   = blockIdx.x * CT;
    const int tid  = threadIdx.x;
    const int lane = tid & 31;
    const int wid  = tid >> 5;
    const int grp  = tid & 3;        // channel quad (0..3)
    const int cq   = grp * 4;        // channel offset within tile
    const int srow = tid >> 2;       // 0..95 spatial phase

    const float* xb = x   + (size_t)b * HW * Cn + c0;
    float*       ob = out + (size_t)b * HW * Cn + c0;

    // ---- Step A: stream x, per-thread running argmax for 4 channels ----
    float bv0 = -CUDART_INF_F, bv1 = -CUDART_INF_F;
    float bv2 = -CUDART_INF_F, bv3 = -CUDART_INF_F;
    int bi0 = 0, bi1 = 0, bi2 = 0, bi3 = 0;

    #pragma unroll 4
    for (int s = srow; s < HW; s += NSP) {
        float4 v = *(const float4*)(xb + (size_t)s * Cn + cq);
        // strict > keeps the earliest index within this thread's ascending s
        if (v.x > bv0) { bv0 = v.x; bi0 = s; }
        if (v.y > bv1) { bv1 = v.y; bi1 = s; }
        if (v.z > bv2) { bv2 = v.z; bi2 = s; }
        if (v.w > bv3) { bv3 = v.w; bi3 = s; }
    }

    // ---- Warp shuffle reduce: lanes {grp, grp+4, ..., grp+28} share channels ----
    const unsigned m = 0xFFFFFFFFu;
    #pragma unroll
    for (int off = 16; off >= 4; off >>= 1) {
        float ov; int oi;
        ov = __shfl_down_sync(m, bv0, off); oi = __shfl_down_sync(m, bi0, off);
        if (ov > bv0 || (ov == bv0 && oi < bi0)) { bv0 = ov; bi0 = oi; }
        ov = __shfl_down_sync(m, bv1, off); oi = __shfl_down_sync(m, bi1, off);
        if (ov > bv1 || (ov == bv1 && oi < bi1)) { bv1 = ov; bi1 = oi; }
        ov = __shfl_down_sync(m, bv2, off); oi = __shfl_down_sync(m, bi2, off);
        if (ov > bv2 || (ov == bv2 && oi < bi2)) { bv2 = ov; bi2 = oi; }
        ov = __shfl_down_sync(m, bv3, off); oi = __shfl_down_sync(m, bi3, off);
        if (ov > bv3 || (ov == bv3 && oi < bi3)) { bv3 = ov; bi3 = oi; }
    }
    if (lane < 4) {   // lane == grp holds warp result for channels cq..cq+3
        pval[(cq + 0) * NW + wid] = bv0; pidx[(cq + 0) * NW + wid] = bi0;
        pval[(cq + 1) * NW + wid] = bv1; pidx[(cq + 1) * NW + wid] = bi1;
        pval[(cq + 2) * NW + wid] = bv2; pidx[(cq + 2) * NW + wid] = bi2;
        pval[(cq + 3) * NW + wid] = bv3; pidx[(cq + 3) * NW + wid] = bi3;
    }
    __syncthreads();

    // ---- Final reduce: 16 threads, NW partials each (tie-break = lowest idx) ----
    if (tid < CT) {
        const float* pv = pval + tid * NW;
        const int*   pi = pidx + tid * NW;
        float bv = -CUDART_INF_F; int bi = HW;
        #pragma unroll
        for (int k = 0; k < NW; ++k) {
            float v = pv[k]; int i = pi[k];
            if (v > bv || (v == bv && i < bi)) { bv = v; bi = i; }
        }
        tbase[tid] = b * HW + bi;
    }
    __syncthreads();

    // ---- Step B: gather template rows into SMEM with XOR swizzle ----
    // Swizzle: float index = cc*TS + (s ^ 8*w), w = (cc>>3)&1.
    // In float4 units: idx4 = s4 ^ (2*w). Makes the 4 channel-quads hit
    // 4 distinct 8-bank blocks in step C -> conflict-free scalar LDS.
    #pragma unroll
    for (int cc = wid; cc < CT; cc += NW) {
        const float4* row = (const float4*)(tp + (size_t)tbase[cc] * HW);
        float* dst = ts + cc * TS;
        const int swz4 = ((cc >> 3) & 1) * 2;
        #pragma unroll
        for (int s4 = lane; s4 < HW / 4; s4 += 32) {
            float4 v = row[s4];
            *(float4*)(dst + (s4 ^ swz4) * 4) = v;
        }
    }
    __syncthreads();

    // ---- Step C: out = relu(x * template); x re-read hits L2 ----
    const int swzs = ((cq >> 3) & 1) * 8;        // same for cq..cq+3 (quad aligned)
    const float* ts0 = ts + (cq + 0) * TS;
    const float* ts1 = ts + (cq + 1) * TS;
    const float* ts2 = ts + (cq + 2) * TS;
    const float* ts3 = ts + (cq + 3) * TS;
    #pragma unroll 4
    for (int s = srow; s < HW; s += NSP) {
        float4 v = *(const float4*)(xb + (size_t)s * Cn + cq);
        const int ss = s ^ swzs;
        float t0 = ts0[ss];
        float t1 = ts1[ss];
        float t2 = ts2[ss];
        float t3 = ts3[ss];
        float4 o;
        o.x = fmaxf(v.x * t0, 0.0f);
        o.y = fmaxf(v.y * t1, 0.0f);
        o.z = fmaxf(v.z * t2, 0.0f);
        o.w = fmaxf(v.w * t3, 0.0f);
        *(float4*)(ob + (size_t)s * Cn + cq) = o;
    }
}

extern "C" void kernel_launch(void* const* d_in, const int* in_sizes, int n_in,
                              void* d_out, int out_size)
{
    const float* x  = (const float*)d_in[0];
    const float* tp = (const float*)d_in[1];
    // Defensive: identify tensors by element count (x: 25,690,112; t_p: 39,337,984)
    if (n_in >= 2 && in_sizes[0] == Bn * HW * HW) {
        const float* t = x; x = tp; tp = t;
    }
    float* out = (float*)d_out;

    cudaFuncSetAttribute(fused_peak_template_relu,
                         cudaFuncAttributeMaxDynamicSharedMemorySize, SMEM_BYTES);

    dim3 grid(Cn / CT, Bn);   // (32, 64) = 2048 blocks
    fused_peak_template_relu<<<grid, NTB, SMEM_BYTES>>>(x, tp, out);
}